// round 1
// baseline (speedup 1.0000x reference)
#include <cuda_runtime.h>
#include <cuda_bf16.h>
#include <math.h>

// Problem constants
#define BB 2
#define SS 2048
#define EE 2048
#define HH 16
#define DD 128
#define MM (BB*SS)   // 4096

// ---------------------------------------------------------------------------
// Scratch (alloc-free: __device__ globals)
// ---------------------------------------------------------------------------
__device__ float g_Q[(size_t)MM * EE];   // Q projection  [B*S, E]
__device__ float g_K[(size_t)MM * DD];   // K projection  [B*S, D]
__device__ float g_V[(size_t)MM * DD];   // V projection  [B*S, D]
__device__ float g_C[(size_t)MM * EE];   // attention out [B*S, E]

// ---------------------------------------------------------------------------
// NT GEMM with bias: C[M,N] = A[M,K] @ B[N,K]^T + bias[N]
// A row-major [M,K], B row-major [N,K] (both K-contiguous), C row-major.
// Tiled with transposed smem staging + register prefetch.
// ---------------------------------------------------------------------------
template<int BM, int BN, int BK, int TM, int TN>
__global__ void __launch_bounds__((BM/TM)*(BN/TN))
gemm_nt_bias(const float* __restrict__ A,
             const float* __restrict__ Bw,
             const float* __restrict__ bias,
             float* __restrict__ C,
             int M, int N, int K)
{
    constexpr int NTH = (BM/TM)*(BN/TN);
    constexpr int LDA = BM + 4;
    constexpr int LDB = BN + 4;
    constexpr int KV4 = BK / 4;            // float4 per row along K
    constexpr int APT = BM * KV4 / NTH;    // A float4 loads per thread
    constexpr int BPT = BN * KV4 / NTH;

    __shared__ __align__(16) float As[BK * LDA];
    __shared__ __align__(16) float Bs[BK * LDB];

    const int tid = threadIdx.x;
    const int tc  = tid % (BN/TN);
    const int tr  = tid / (BN/TN);
    const int m0  = blockIdx.y * BM;
    const int n0  = blockIdx.x * BN;

    const float* Ab = A  + (size_t)m0 * K;
    const float* Bb = Bw + (size_t)n0 * K;

    float4 ar[APT], br[BPT];
    float  acc[TM][TN];
#pragma unroll
    for (int i = 0; i < TM; i++)
#pragma unroll
        for (int j = 0; j < TN; j++) acc[i][j] = 0.f;

    auto loadA = [&](int kt) {
#pragma unroll
        for (int u = 0; u < APT; u++) {
            int idx = tid + u*NTH;
            int row = idx / KV4;
            int c4  = idx % KV4;
            ar[u] = *reinterpret_cast<const float4*>(Ab + (size_t)row*K + kt*BK + c4*4);
        }
    };
    auto loadB = [&](int kt) {
#pragma unroll
        for (int u = 0; u < BPT; u++) {
            int idx = tid + u*NTH;
            int row = idx / KV4;
            int c4  = idx % KV4;
            br[u] = *reinterpret_cast<const float4*>(Bb + (size_t)row*K + kt*BK + c4*4);
        }
    };

    loadA(0); loadB(0);
    const int nk = K / BK;

    for (int kt = 0; kt < nk; kt++) {
        // stage regs -> smem (transposed: [k][m])
#pragma unroll
        for (int u = 0; u < APT; u++) {
            int idx = tid + u*NTH;
            int row = idx / KV4;
            int c4  = idx % KV4;
            As[(c4*4+0)*LDA + row] = ar[u].x;
            As[(c4*4+1)*LDA + row] = ar[u].y;
            As[(c4*4+2)*LDA + row] = ar[u].z;
            As[(c4*4+3)*LDA + row] = ar[u].w;
        }
#pragma unroll
        for (int u = 0; u < BPT; u++) {
            int idx = tid + u*NTH;
            int row = idx / KV4;
            int c4  = idx % KV4;
            Bs[(c4*4+0)*LDB + row] = br[u].x;
            Bs[(c4*4+1)*LDB + row] = br[u].y;
            Bs[(c4*4+2)*LDB + row] = br[u].z;
            Bs[(c4*4+3)*LDB + row] = br[u].w;
        }
        __syncthreads();

        if (kt + 1 < nk) { loadA(kt+1); loadB(kt+1); }

#pragma unroll
        for (int k = 0; k < BK; k++) {
            float a[TM], b[TN];
#pragma unroll
            for (int i = 0; i < TM; i += 4) {
                float4 t = *reinterpret_cast<const float4*>(&As[k*LDA + tr*TM + i]);
                a[i+0]=t.x; a[i+1]=t.y; a[i+2]=t.z; a[i+3]=t.w;
            }
#pragma unroll
            for (int j = 0; j < TN; j += 4) {
                float4 t = *reinterpret_cast<const float4*>(&Bs[k*LDB + tc*TN + j]);
                b[j+0]=t.x; b[j+1]=t.y; b[j+2]=t.z; b[j+3]=t.w;
            }
#pragma unroll
            for (int i = 0; i < TM; i++)
#pragma unroll
                for (int j = 0; j < TN; j++)
                    acc[i][j] = fmaf(a[i], b[j], acc[i][j]);
        }
        __syncthreads();
    }

    // epilogue: add bias, vectorized store
#pragma unroll
    for (int i = 0; i < TM; i++) {
        size_t crow = (size_t)(m0 + tr*TM + i) * N + n0 + tc*TN;
#pragma unroll
        for (int j = 0; j < TN; j += 4) {
            float4 o;
            o.x = acc[i][j+0] + bias[n0 + tc*TN + j+0];
            o.y = acc[i][j+1] + bias[n0 + tc*TN + j+1];
            o.z = acc[i][j+2] + bias[n0 + tc*TN + j+2];
            o.w = acc[i][j+3] + bias[n0 + tc*TN + j+3];
            *reinterpret_cast<float4*>(C + crow + j) = o;
        }
    }
}

// ---------------------------------------------------------------------------
// Causal MQA flash attention (fp32, online softmax)
// Q: [B*S, E] viewed as [B,S,H,D]; K,V: [B*S, D]; O: [B*S, E] = [B,S,H,D]
// grid (S/64, H, B), block 256. Br=Bc=64.
// Dynamic smem: Qs[64][132] + KV[64][132] (K uses stride 129) + Ps[64][65]
// ---------------------------------------------------------------------------
#define SMEM_ATTN ((64*132*2 + 64*65) * 4)

__global__ void __launch_bounds__(256)
mqa_attn(const float* __restrict__ Q, const float* __restrict__ Kb,
         const float* __restrict__ Vb, float* __restrict__ O)
{
    extern __shared__ __align__(16) float sm[];
    float* Qs = sm;               // stride 132
    float* KV = sm + 64*132;      // K at stride 129 (scalar), V at stride 132 (vec4)
    float* Ps = sm + 2*64*132;    // stride 65

    const int qt = blockIdx.x;
    const int h  = blockIdx.y;
    const int b  = blockIdx.z;
    const int q0 = qt * 64;

    const int tid = threadIdx.x;
    const int tx  = tid & 15;
    const int ty  = tid >> 4;

    const float scale = 0.08838834764831845f;  // 1/sqrt(128)

    const float* Qp = Q  + ((size_t)(b*SS + q0))*EE + h*DD;
    const float* Kp = Kb + (size_t)b*SS*DD;
    const float* Vp = Vb + (size_t)b*SS*DD;

    // load Q tile (pre-scaled)
    for (int i = tid; i < 64*32; i += 256) {
        int r = i >> 5, c4 = (i & 31) * 4;
        float4 v = *reinterpret_cast<const float4*>(Qp + (size_t)r*EE + c4);
        v.x *= scale; v.y *= scale; v.z *= scale; v.w *= scale;
        *reinterpret_cast<float4*>(&Qs[r*132 + c4]) = v;
    }

    float acc[4][8];
#pragma unroll
    for (int i = 0; i < 4; i++)
#pragma unroll
        for (int c = 0; c < 8; c++) acc[i][c] = 0.f;
    float mrow[4] = {-1e30f, -1e30f, -1e30f, -1e30f};
    float lrow[4] = {0.f, 0.f, 0.f, 0.f};

    for (int kt = 0; kt <= qt; kt++) {
        const int k0 = kt * 64;

        __syncthreads();   // prior PV reads of KV done; Q tile visible (1st iter)
        // load K tile, scalar stores at odd stride 129 (conflict-free b-reads)
        for (int i = tid; i < 64*32; i += 256) {
            int r = i >> 5, c4 = (i & 31) * 4;
            float4 v = *reinterpret_cast<const float4*>(Kp + (size_t)(k0+r)*DD + c4);
            KV[r*129 + c4+0] = v.x;
            KV[r*129 + c4+1] = v.y;
            KV[r*129 + c4+2] = v.z;
            KV[r*129 + c4+3] = v.w;
        }
        __syncthreads();

        // scores: s[i][j] = q_row(ty*4+i) . k_col(j*16+tx)
        float s[4][4];
#pragma unroll
        for (int i = 0; i < 4; i++)
#pragma unroll
            for (int j = 0; j < 4; j++) s[i][j] = 0.f;

#pragma unroll 4
        for (int k = 0; k < DD; k++) {
            float a0 = Qs[(ty*4+0)*132 + k];
            float a1 = Qs[(ty*4+1)*132 + k];
            float a2 = Qs[(ty*4+2)*132 + k];
            float a3 = Qs[(ty*4+3)*132 + k];
            float b0 = KV[( 0 + tx)*129 + k];
            float b1 = KV[(16 + tx)*129 + k];
            float b2 = KV[(32 + tx)*129 + k];
            float b3 = KV[(48 + tx)*129 + k];
            s[0][0] = fmaf(a0,b0,s[0][0]); s[0][1] = fmaf(a0,b1,s[0][1]);
            s[0][2] = fmaf(a0,b2,s[0][2]); s[0][3] = fmaf(a0,b3,s[0][3]);
            s[1][0] = fmaf(a1,b0,s[1][0]); s[1][1] = fmaf(a1,b1,s[1][1]);
            s[1][2] = fmaf(a1,b2,s[1][2]); s[1][3] = fmaf(a1,b3,s[1][3]);
            s[2][0] = fmaf(a2,b0,s[2][0]); s[2][1] = fmaf(a2,b1,s[2][1]);
            s[2][2] = fmaf(a2,b2,s[2][2]); s[2][3] = fmaf(a2,b3,s[2][3]);
            s[3][0] = fmaf(a3,b0,s[3][0]); s[3][1] = fmaf(a3,b1,s[3][1]);
            s[3][2] = fmaf(a3,b2,s[3][2]); s[3][3] = fmaf(a3,b3,s[3][3]);
        }

        // causal mask on diagonal tile
        if (kt == qt) {
#pragma unroll
            for (int i = 0; i < 4; i++)
#pragma unroll
                for (int j = 0; j < 4; j++)
                    if (j*16 + tx > ty*4 + i) s[i][j] = -1e30f;
        }

        // online softmax update (row stats reduced across the 16 tx lanes)
#pragma unroll
        for (int i = 0; i < 4; i++) {
            float mt = fmaxf(fmaxf(s[i][0], s[i][1]), fmaxf(s[i][2], s[i][3]));
#pragma unroll
            for (int off = 8; off >= 1; off >>= 1)
                mt = fmaxf(mt, __shfl_xor_sync(0xffffffffu, mt, off));
            float mnew = fmaxf(mrow[i], mt);
            float corr = __expf(mrow[i] - mnew);
            mrow[i] = mnew;
            float ps = 0.f;
#pragma unroll
            for (int j = 0; j < 4; j++) {
                float p = __expf(s[i][j] - mnew);
                s[i][j] = p;
                ps += p;
            }
#pragma unroll
            for (int off = 8; off >= 1; off >>= 1)
                ps += __shfl_xor_sync(0xffffffffu, ps, off);
            lrow[i] = lrow[i]*corr + ps;
#pragma unroll
            for (int c = 0; c < 8; c++) acc[i][c] *= corr;
#pragma unroll
            for (int j = 0; j < 4; j++)
                Ps[(ty*4+i)*65 + j*16 + tx] = s[i][j];
        }
        __syncthreads();   // Ps visible; all K reads done -> safe to overwrite KV

        // load V tile, float4 at stride 132
        for (int i = tid; i < 64*32; i += 256) {
            int r = i >> 5, c4 = (i & 31) * 4;
            *reinterpret_cast<float4*>(&KV[r*132 + c4]) =
                *reinterpret_cast<const float4*>(Vp + (size_t)(k0+r)*DD + c4);
        }
        __syncthreads();

        // O += P @ V : acc rows ty*4+i, cols tx*8..tx*8+7
#pragma unroll 2
        for (int j = 0; j < 64; j++) {
            float p0 = Ps[(ty*4+0)*65 + j];
            float p1 = Ps[(ty*4+1)*65 + j];
            float p2 = Ps[(ty*4+2)*65 + j];
            float p3 = Ps[(ty*4+3)*65 + j];
            float4 v0 = *reinterpret_cast<const float4*>(&KV[j*132 + tx*8]);
            float4 v1 = *reinterpret_cast<const float4*>(&KV[j*132 + tx*8 + 4]);
            acc[0][0] = fmaf(p0, v0.x, acc[0][0]); acc[0][1] = fmaf(p0, v0.y, acc[0][1]);
            acc[0][2] = fmaf(p0, v0.z, acc[0][2]); acc[0][3] = fmaf(p0, v0.w, acc[0][3]);
            acc[0][4] = fmaf(p0, v1.x, acc[0][4]); acc[0][5] = fmaf(p0, v1.y, acc[0][5]);
            acc[0][6] = fmaf(p0, v1.z, acc[0][6]); acc[0][7] = fmaf(p0, v1.w, acc[0][7]);
            acc[1][0] = fmaf(p1, v0.x, acc[1][0]); acc[1][1] = fmaf(p1, v0.y, acc[1][1]);
            acc[1][2] = fmaf(p1, v0.z, acc[1][2]); acc[1][3] = fmaf(p1, v0.w, acc[1][3]);
            acc[1][4] = fmaf(p1, v1.x, acc[1][4]); acc[1][5] = fmaf(p1, v1.y, acc[1][5]);
            acc[1][6] = fmaf(p1, v1.z, acc[1][6]); acc[1][7] = fmaf(p1, v1.w, acc[1][7]);
            acc[2][0] = fmaf(p2, v0.x, acc[2][0]); acc[2][1] = fmaf(p2, v0.y, acc[2][1]);
            acc[2][2] = fmaf(p2, v0.z, acc[2][2]); acc[2][3] = fmaf(p2, v0.w, acc[2][3]);
            acc[2][4] = fmaf(p2, v1.x, acc[2][4]); acc[2][5] = fmaf(p2, v1.y, acc[2][5]);
            acc[2][6] = fmaf(p2, v1.z, acc[2][6]); acc[2][7] = fmaf(p2, v1.w, acc[2][7]);
            acc[3][0] = fmaf(p3, v0.x, acc[3][0]); acc[3][1] = fmaf(p3, v0.y, acc[3][1]);
            acc[3][2] = fmaf(p3, v0.z, acc[3][2]); acc[3][3] = fmaf(p3, v0.w, acc[3][3]);
            acc[3][4] = fmaf(p3, v1.x, acc[3][4]); acc[3][5] = fmaf(p3, v1.y, acc[3][5]);
            acc[3][6] = fmaf(p3, v1.z, acc[3][6]); acc[3][7] = fmaf(p3, v1.w, acc[3][7]);
        }
    }

    // normalize + store
    float* Op = O + ((size_t)(b*SS + q0))*EE + h*DD;
#pragma unroll
    for (int i = 0; i < 4; i++) {
        float inv = 1.f / lrow[i];
        float4 o0, o1;
        o0.x = acc[i][0]*inv; o0.y = acc[i][1]*inv;
        o0.z = acc[i][2]*inv; o0.w = acc[i][3]*inv;
        o1.x = acc[i][4]*inv; o1.y = acc[i][5]*inv;
        o1.z = acc[i][6]*inv; o1.w = acc[i][7]*inv;
        *reinterpret_cast<float4*>(Op + (size_t)(ty*4+i)*EE + tx*8)     = o0;
        *reinterpret_cast<float4*>(Op + (size_t)(ty*4+i)*EE + tx*8 + 4) = o1;
    }
}

// ---------------------------------------------------------------------------
// kernel_launch
// ---------------------------------------------------------------------------
extern "C" void kernel_launch(void* const* d_in, const int* in_sizes, int n_in,
                              void* d_out, int out_size)
{
    const float* input = (const float*)d_in[0];
    const float* kv    = (const float*)d_in[1];
    const float* Wq    = (const float*)d_in[2];
    const float* bq    = (const float*)d_in[3];
    const float* Wk    = (const float*)d_in[4];
    const float* bk    = (const float*)d_in[5];
    const float* Wv    = (const float*)d_in[6];
    const float* bv    = (const float*)d_in[7];
    const float* Wo    = (const float*)d_in[8];
    const float* bo    = (const float*)d_in[9];
    float* out = (float*)d_out;

    float *gq, *gk, *gv, *gc;
    cudaGetSymbolAddress((void**)&gq, g_Q);
    cudaGetSymbolAddress((void**)&gk, g_K);
    cudaGetSymbolAddress((void**)&gv, g_V);
    cudaGetSymbolAddress((void**)&gc, g_C);

    // Q projection: [4096,2048] = input @ Wq^T + bq
    {
        dim3 grid(EE/128, MM/128);
        gemm_nt_bias<128,128,16,8,8><<<grid, 256>>>(input, Wq, bq, gq, MM, EE, EE);
    }
    // K,V projections: [4096,128]
    {
        dim3 grid(DD/64, MM/64);
        gemm_nt_bias<64,64,16,4,4><<<grid, 256>>>(kv, Wk, bk, gk, MM, DD, EE);
        gemm_nt_bias<64,64,16,4,4><<<grid, 256>>>(kv, Wv, bv, gv, MM, DD, EE);
    }
    // attention
    {
        cudaFuncSetAttribute(mqa_attn, cudaFuncAttributeMaxDynamicSharedMemorySize,
                             SMEM_ATTN);
        dim3 grid(SS/64, HH, BB);
        mqa_attn<<<grid, 256, SMEM_ATTN>>>(gq, gk, gv, gc);
    }
    // output projection into d_out
    {
        dim3 grid(EE/128, MM/128);
        gemm_nt_bias<128,128,16,8,8><<<grid, 256>>>(gc, Wo, bo, out, MM, EE, EE);
    }
}

// round 5
// speedup vs baseline: 4.5862x; 4.5862x over previous
#include <cuda_runtime.h>
#include <cuda_bf16.h>
#include <cstdint>
#include <math.h>

// Problem constants
#define BB 2
#define SS 2048
#define EE 2048
#define HH 16
#define DD 128
#define MM (BB*SS)   // 4096

// ---------------------------------------------------------------------------
// Scratch (alloc-free: __device__ globals)
// ---------------------------------------------------------------------------
__device__ float g_Q  [(size_t)MM * EE];  // Q projection (fp32)
__device__ float g_K  [(size_t)MM * DD];
__device__ float g_V  [(size_t)MM * DD];
__device__ float g_C  [(size_t)MM * EE];  // attention out (tf32-rounded at store)
__device__ float g_Xq [(size_t)MM * EE];  // tf32-rounded activations/weights
__device__ float g_Xkv[(size_t)MM * EE];
__device__ float g_Wq [(size_t)EE * EE];
__device__ float g_Wk [(size_t)DD * EE];
__device__ float g_Wv [(size_t)DD * EE];
__device__ float g_Wo [(size_t)EE * EE];

// ---------------------------------------------------------------------------
// Base-target-safe PTX helpers (sm_80-era: cp.async, mma.sync, cvt.tf32)
// ---------------------------------------------------------------------------
__device__ __forceinline__ uint32_t smem_u32(const void* p) {
    uint32_t a;
    asm("{ .reg .u64 t; cvta.to.shared.u64 t, %1; cvt.u32.u64 %0, t; }"
        : "=r"(a) : "l"(p));
    return a;
}

#define CP_ASYNC16(dst, src) \
    asm volatile("cp.async.cg.shared.global [%0], [%1], 16;" \
                 :: "r"(dst), "l"(src) : "memory")
#define CP_COMMIT() asm volatile("cp.async.commit_group;" ::: "memory")
#define CP_WAIT(n)  asm volatile("cp.async.wait_group %0;" :: "n"(n) : "memory")

__device__ __forceinline__ float tf32r(float x) {
    uint32_t u;
    asm("cvt.rna.tf32.f32 %0, %1;" : "=r"(u) : "f"(x));
    return __uint_as_float(u);
}
__device__ __forceinline__ float4 tf32r4(float4 v) {
    v.x = tf32r(v.x); v.y = tf32r(v.y); v.z = tf32r(v.z); v.w = tf32r(v.w);
    return v;
}
__device__ __forceinline__ uint32_t fbits(float x) { return __float_as_uint(x); }

// m16n8k8 tf32 MMA, fp32 accum, D==C in-place
__device__ __forceinline__ void mma_tf32(float d[4], const uint32_t a[4],
                                         const uint32_t b[2]) {
    asm volatile(
        "mma.sync.aligned.m16n8k8.row.col.f32.tf32.tf32.f32 "
        "{%0,%1,%2,%3}, {%4,%5,%6,%7}, {%8,%9}, {%0,%1,%2,%3};"
        : "+f"(d[0]), "+f"(d[1]), "+f"(d[2]), "+f"(d[3])
        : "r"(a[0]), "r"(a[1]), "r"(a[2]), "r"(a[3]),
          "r"(b[0]), "r"(b[1]));
}

// ---------------------------------------------------------------------------
// fp32 -> tf32 rounding pass
// ---------------------------------------------------------------------------
__global__ void __launch_bounds__(256)
cvt_tf32(const float* __restrict__ in, float* __restrict__ out, int n4)
{
    int i = blockIdx.x * 256 + threadIdx.x;
    if (i < n4) {
        float4 v = reinterpret_cast<const float4*>(in)[i];
        reinterpret_cast<float4*>(out)[i] = tf32r4(v);
    }
}

// ---------------------------------------------------------------------------
// Tensor-core tf32 GEMM: C[M,N] = A[M,K] @ B[N,K]^T + bias[N]
// A,B pre-rounded tf32 (fp32 storage, both K-contiguous).
// CTA tile 128x128x32, 8 warps (2m x 4n -> warp tile 64x32).
// 3-stage cp.async pipeline. smem rows padded to 36 floats (conflict-free
// single-phase fragment LDS: bank = 4*row + k for lanes of a quad-group).
// ---------------------------------------------------------------------------
#define GBK 32
#define GROW 36                         // floats per smem row (32 + 4 pad)
#define GTILE (128*GROW)                // floats per operand per stage
#define GSTAGE (2*GTILE)
#define GSTAGES 3
#define SMEM_GEMM (GSTAGES*GSTAGE*4)    // 110592 bytes

__global__ void __launch_bounds__(256, 2)
gemm_mma_tf32(const float* __restrict__ A, const float* __restrict__ Bw,
              const float* __restrict__ bias, float* __restrict__ C,
              int M, int N, int K)
{
    extern __shared__ __align__(16) float sg[];
    const uint32_t smem_base = smem_u32(sg);
    const int tid = threadIdx.x;
    const int wid = tid >> 5, lane = tid & 31;
    const int g = lane >> 2, t = lane & 3;
    const int wm = wid >> 2, wn = wid & 3;      // 2 x 4 warp grid
    const int m0 = blockIdx.y * 128, n0 = blockIdx.x * 128;
    const int m0w = wm * 64, n0w = wn * 32;

    const char* Ab = (const char*)(A  + (size_t)m0 * K);
    const char* Bb = (const char*)(Bw + (size_t)n0 * K);
    const size_t rowKB = (size_t)K * 4;
    const int NK = K / GBK;

    // stage loader: 128 rows x 8 chunks(16B) per operand; 4 chunks/thread each
    auto stage_load = [&](int kt, int buf) {
        uint32_t sA = smem_base + (uint32_t)(buf*GSTAGE)*4;
        uint32_t sB = sA + GTILE*4;
        const char* gA = Ab + (size_t)kt * (GBK*4);
        const char* gB = Bb + (size_t)kt * (GBK*4);
#pragma unroll
        for (int i = 0; i < 4; i++) {
            int c   = tid + i*256;
            int row = c >> 3;
            int ch  = c & 7;
            uint32_t d = (uint32_t)row*(GROW*4) + (uint32_t)ch*16;
            CP_ASYNC16(sA + d, gA + (size_t)row*rowKB + ch*16);
            CP_ASYNC16(sB + d, gB + (size_t)row*rowKB + ch*16);
        }
    };

    stage_load(0, 0); CP_COMMIT();
    stage_load(1, 1); CP_COMMIT();

    float acc[4][4][4];
#pragma unroll
    for (int mf = 0; mf < 4; mf++)
#pragma unroll
        for (int nf = 0; nf < 4; nf++)
#pragma unroll
            for (int r = 0; r < 4; r++) acc[mf][nf][r] = 0.f;

    for (int kt = 0; kt < NK; kt++) {
        CP_WAIT(1);
        __syncthreads();
        if (kt + 2 < NK) stage_load(kt + 2, (kt + 2) % GSTAGES);
        CP_COMMIT();

        const float* As = sg + (kt % GSTAGES)*GSTAGE;
        const float* Bs = As + GTILE;

#pragma unroll
        for (int k8 = 0; k8 < GBK/8; k8++) {
            const int kk = k8*8;
            uint32_t a[4][4];
#pragma unroll
            for (int mf = 0; mf < 4; mf++) {
                const float* ap = As + (m0w + mf*16)*GROW + kk;
                a[mf][0] = fbits(ap[(g    )*GROW + t    ]);
                a[mf][1] = fbits(ap[(g + 8)*GROW + t    ]);
                a[mf][2] = fbits(ap[(g    )*GROW + t + 4]);
                a[mf][3] = fbits(ap[(g + 8)*GROW + t + 4]);
            }
            uint32_t b[4][2];
#pragma unroll
            for (int nf = 0; nf < 4; nf++) {
                const float* bp = Bs + (n0w + nf*8 + g)*GROW + kk;
                b[nf][0] = fbits(bp[t    ]);
                b[nf][1] = fbits(bp[t + 4]);
            }
#pragma unroll
            for (int mf = 0; mf < 4; mf++)
#pragma unroll
                for (int nf = 0; nf < 4; nf++)
                    mma_tf32(acc[mf][nf], a[mf], b[nf]);
        }
    }

    // epilogue: bias add + store (c0/c1 at row g, c2/c3 at row g+8)
#pragma unroll
    for (int mf = 0; mf < 4; mf++) {
        const int r0 = m0 + m0w + mf*16 + g;
#pragma unroll
        for (int nf = 0; nf < 4; nf++) {
            const int col = n0 + n0w + nf*8 + t*2;
            float2 bb = *reinterpret_cast<const float2*>(bias + col);
            float2 v0 = { acc[mf][nf][0] + bb.x, acc[mf][nf][1] + bb.y };
            float2 v1 = { acc[mf][nf][2] + bb.x, acc[mf][nf][3] + bb.y };
            *reinterpret_cast<float2*>(C + (size_t)r0*N + col)     = v0;
            *reinterpret_cast<float2*>(C + (size_t)(r0+8)*N + col) = v1;
        }
    }
}

// ---------------------------------------------------------------------------
// Tensor-core causal MQA flash attention (tf32 mma, fp32 softmax/accum)
// Br=64 (4 warps x m16 rows), Bc=32 keys/tile, D=128.
// grid (S/64, H, B), block 128.
// smem: Qs[64][132] Ks[32][132] Vs[32][132] Ps[4][16][36]  = 76.8 KB
// ---------------------------------------------------------------------------
#define AROW 132
#define SMEM_ATTN ((64*AROW + 32*AROW + 32*AROW + 4*16*36) * 4)

__global__ void __launch_bounds__(128, 2)
mqa_attn_tc(const float* __restrict__ Q, const float* __restrict__ Kb,
            const float* __restrict__ Vb, float* __restrict__ O)
{
    extern __shared__ __align__(16) float sa[];
    float* Qs = sa;                 // [64][AROW]
    float* Ks = Qs + 64*AROW;       // [32][AROW]
    float* Vs = Ks + 32*AROW;       // [32][AROW]
    float* Ps = Vs + 32*AROW;       // [4][16][36]

    const int qt = blockIdx.x, h = blockIdx.y, b = blockIdx.z;
    const int q0 = qt * 64;
    const int tid = threadIdx.x;
    const int w = tid >> 5, lane = tid & 31;
    const int g = lane >> 2, t = lane & 3;
    float* Pw = Ps + w*16*36;

    const float scale = 0.08838834764831845f;   // 1/sqrt(128)
    const float* Qp = Q  + ((size_t)(b*SS + q0))*EE + h*DD;
    const float* Kp = Kb + (size_t)b*SS*DD;
    const float* Vp = Vb + (size_t)b*SS*DD;

    // load + scale + tf32-round Q tile
    for (int i = tid; i < 64*32; i += 128) {
        int r = i >> 5, c4 = (i & 31)*4;
        float4 v = *reinterpret_cast<const float4*>(Qp + (size_t)r*EE + c4);
        v.x = tf32r(v.x*scale); v.y = tf32r(v.y*scale);
        v.z = tf32r(v.z*scale); v.w = tf32r(v.w*scale);
        *reinterpret_cast<float4*>(Qs + r*AROW + c4) = v;
    }

    float o[16][4];
#pragma unroll
    for (int df = 0; df < 16; df++)
#pragma unroll
        for (int r = 0; r < 4; r++) o[df][r] = 0.f;
    float m0r = -1e30f, m1r = -1e30f, l0r = 0.f, l1r = 0.f;

    const float* Qw = Qs + (w*16)*AROW;
    const int nk = 2*qt + 2;

    for (int kt = 0; kt < nk; kt++) {
        const int k0 = kt * 32;
        __syncthreads();   // prior tile's mma reads of Ks/Vs complete
        for (int i = tid; i < 32*32; i += 128) {
            int r = i >> 5, c4 = (i & 31)*4;
            float4 kv4 = tf32r4(*reinterpret_cast<const float4*>(
                                Kp + (size_t)(k0+r)*DD + c4));
            *reinterpret_cast<float4*>(Ks + r*AROW + c4) = kv4;
            float4 vv = tf32r4(*reinterpret_cast<const float4*>(
                               Vp + (size_t)(k0+r)*DD + c4));
            *reinterpret_cast<float4*>(Vs + r*AROW + c4) = vv;
        }
        __syncthreads();

        // ---- S = Q K^T  (4 n-frags of n8 over 32 keys) ----
        float s[4][4];
#pragma unroll
        for (int nf = 0; nf < 4; nf++)
#pragma unroll
            for (int r = 0; r < 4; r++) s[nf][r] = 0.f;

#pragma unroll
        for (int k8 = 0; k8 < 16; k8++) {
            const int kk = k8*8;
            uint32_t a[4];
            a[0] = fbits(Qw[(g    )*AROW + kk + t    ]);
            a[1] = fbits(Qw[(g + 8)*AROW + kk + t    ]);
            a[2] = fbits(Qw[(g    )*AROW + kk + t + 4]);
            a[3] = fbits(Qw[(g + 8)*AROW + kk + t + 4]);
#pragma unroll
            for (int nf = 0; nf < 4; nf++) {
                uint32_t bb[2];
                bb[0] = fbits(Ks[(nf*8 + g)*AROW + kk + t    ]);
                bb[1] = fbits(Ks[(nf*8 + g)*AROW + kk + t + 4]);
                mma_tf32(s[nf], a, bb);
            }
        }

        // ---- causal mask ----
        if (k0 + 31 > q0 + w*16) {
            const int r0 = q0 + w*16 + g, r1 = r0 + 8;
#pragma unroll
            for (int nf = 0; nf < 4; nf++) {
                const int c0 = k0 + nf*8 + t*2, c1 = c0 + 1;
                if (c0 > r0) s[nf][0] = -1e30f;
                if (c1 > r0) s[nf][1] = -1e30f;
                if (c0 > r1) s[nf][2] = -1e30f;
                if (c1 > r1) s[nf][3] = -1e30f;
            }
        }

        // ---- online softmax: row g (regs 0,1) ----
        {
            float mt = fmaxf(fmaxf(s[0][0], s[0][1]), fmaxf(s[1][0], s[1][1]));
            mt = fmaxf(mt, fmaxf(fmaxf(s[2][0], s[2][1]), fmaxf(s[3][0], s[3][1])));
            mt = fmaxf(mt, __shfl_xor_sync(0xffffffffu, mt, 1));
            mt = fmaxf(mt, __shfl_xor_sync(0xffffffffu, mt, 2));
            float mn = fmaxf(m0r, mt);
            float corr = __expf(m0r - mn);
            m0r = mn;
            float ps = 0.f;
#pragma unroll
            for (int nf = 0; nf < 4; nf++) {
                s[nf][0] = __expf(s[nf][0] - mn); ps += s[nf][0];
                s[nf][1] = __expf(s[nf][1] - mn); ps += s[nf][1];
            }
            ps += __shfl_xor_sync(0xffffffffu, ps, 1);
            ps += __shfl_xor_sync(0xffffffffu, ps, 2);
            l0r = l0r*corr + ps;
#pragma unroll
            for (int df = 0; df < 16; df++) { o[df][0] *= corr; o[df][1] *= corr; }
#pragma unroll
            for (int nf = 0; nf < 4; nf++) {
                float2 p = { tf32r(s[nf][0]), tf32r(s[nf][1]) };
                *reinterpret_cast<float2*>(Pw + g*36 + nf*8 + t*2) = p;
            }
        }
        // ---- row g+8 (regs 2,3) ----
        {
            float mt = fmaxf(fmaxf(s[0][2], s[0][3]), fmaxf(s[1][2], s[1][3]));
            mt = fmaxf(mt, fmaxf(fmaxf(s[2][2], s[2][3]), fmaxf(s[3][2], s[3][3])));
            mt = fmaxf(mt, __shfl_xor_sync(0xffffffffu, mt, 1));
            mt = fmaxf(mt, __shfl_xor_sync(0xffffffffu, mt, 2));
            float mn = fmaxf(m1r, mt);
            float corr = __expf(m1r - mn);
            m1r = mn;
            float ps = 0.f;
#pragma unroll
            for (int nf = 0; nf < 4; nf++) {
                s[nf][2] = __expf(s[nf][2] - mn); ps += s[nf][2];
                s[nf][3] = __expf(s[nf][3] - mn); ps += s[nf][3];
            }
            ps += __shfl_xor_sync(0xffffffffu, ps, 1);
            ps += __shfl_xor_sync(0xffffffffu, ps, 2);
            l1r = l1r*corr + ps;
#pragma unroll
            for (int df = 0; df < 16; df++) { o[df][2] *= corr; o[df][3] *= corr; }
#pragma unroll
            for (int nf = 0; nf < 4; nf++) {
                float2 p = { tf32r(s[nf][2]), tf32r(s[nf][3]) };
                *reinterpret_cast<float2*>(Pw + (g+8)*36 + nf*8 + t*2) = p;
            }
        }
        __syncwarp();   // Ps is warp-private: warp-level visibility suffices

        // ---- O += P V ----
#pragma unroll
        for (int j8 = 0; j8 < 4; j8++) {
            const int jj = j8*8;
            uint32_t a[4];
            a[0] = fbits(Pw[(g    )*36 + jj + t    ]);
            a[1] = fbits(Pw[(g + 8)*36 + jj + t    ]);
            a[2] = fbits(Pw[(g    )*36 + jj + t + 4]);
            a[3] = fbits(Pw[(g + 8)*36 + jj + t + 4]);
#pragma unroll
            for (int df = 0; df < 16; df++) {
                uint32_t bb[2];
                bb[0] = fbits(Vs[(jj + t    )*AROW + df*8 + g]);
                bb[1] = fbits(Vs[(jj + t + 4)*AROW + df*8 + g]);
                mma_tf32(o[df], a, bb);
            }
        }
    }

    // normalize + tf32-round + store (O feeds the tf32 O-projection)
    const float inv0 = 1.f / l0r, inv1 = 1.f / l1r;
    float* Op = O + ((size_t)(b*SS + q0 + w*16))*EE + h*DD;
#pragma unroll
    for (int df = 0; df < 16; df++) {
        const int col = df*8 + t*2;
        float2 v0 = { tf32r(o[df][0]*inv0), tf32r(o[df][1]*inv0) };
        float2 v1 = { tf32r(o[df][2]*inv1), tf32r(o[df][3]*inv1) };
        *reinterpret_cast<float2*>(Op + (size_t)(g    )*EE + col) = v0;
        *reinterpret_cast<float2*>(Op + (size_t)(g + 8)*EE + col) = v1;
    }
}

// ---------------------------------------------------------------------------
// kernel_launch
// ---------------------------------------------------------------------------
extern "C" void kernel_launch(void* const* d_in, const int* in_sizes, int n_in,
                              void* d_out, int out_size)
{
    const float* input = (const float*)d_in[0];
    const float* kv    = (const float*)d_in[1];
    const float* Wq    = (const float*)d_in[2];
    const float* bq    = (const float*)d_in[3];
    const float* Wk    = (const float*)d_in[4];
    const float* bk    = (const float*)d_in[5];
    const float* Wv    = (const float*)d_in[6];
    const float* bv    = (const float*)d_in[7];
    const float* Wo    = (const float*)d_in[8];
    const float* bo    = (const float*)d_in[9];
    float* out = (float*)d_out;

    float *gq, *gk, *gv, *gc, *xq, *xkv, *wq, *wk, *wv, *wo;
    cudaGetSymbolAddress((void**)&gq,  g_Q);
    cudaGetSymbolAddress((void**)&gk,  g_K);
    cudaGetSymbolAddress((void**)&gv,  g_V);
    cudaGetSymbolAddress((void**)&gc,  g_C);
    cudaGetSymbolAddress((void**)&xq,  g_Xq);
    cudaGetSymbolAddress((void**)&xkv, g_Xkv);
    cudaGetSymbolAddress((void**)&wq,  g_Wq);
    cudaGetSymbolAddress((void**)&wk,  g_Wk);
    cudaGetSymbolAddress((void**)&wv,  g_Wv);
    cudaGetSymbolAddress((void**)&wo,  g_Wo);

    cudaFuncSetAttribute(gemm_mma_tf32,
                         cudaFuncAttributeMaxDynamicSharedMemorySize, SMEM_GEMM);
    cudaFuncSetAttribute(mqa_attn_tc,
                         cudaFuncAttributeMaxDynamicSharedMemorySize, SMEM_ATTN);

    // tf32 rounding for GEMM operands (attention rounds its own inputs/outputs)
    {
        int n4 = MM*EE/4;
        cvt_tf32<<<(n4+255)/256, 256>>>(input, xq,  n4);
        cvt_tf32<<<(n4+255)/256, 256>>>(kv,    xkv, n4);
        int w4 = EE*EE/4;
        cvt_tf32<<<(w4+255)/256, 256>>>(Wq, wq, w4);
        cvt_tf32<<<(w4+255)/256, 256>>>(Wo, wo, w4);
        int s4 = DD*EE/4;
        cvt_tf32<<<(s4+255)/256, 256>>>(Wk, wk, s4);
        cvt_tf32<<<(s4+255)/256, 256>>>(Wv, wv, s4);
    }

    // projections (tensor cores)
    {
        dim3 gqg(EE/128, MM/128);
        gemm_mma_tf32<<<gqg, 256, SMEM_GEMM>>>(xq, wq, bq, gq, MM, EE, EE);
        dim3 gkvg(DD/128, MM/128);
        gemm_mma_tf32<<<gkvg, 256, SMEM_GEMM>>>(xkv, wk, bk, gk, MM, DD, EE);
        gemm_mma_tf32<<<gkvg, 256, SMEM_GEMM>>>(xkv, wv, bv, gv, MM, DD, EE);
    }

    // attention (tensor cores)
    {
        dim3 grid(SS/64, HH, BB);
        mqa_attn_tc<<<grid, 128, SMEM_ATTN>>>(gq, gk, gv, gc);
    }

    // output projection into d_out
    {
        dim3 gog(EE/128, MM/128);
        gemm_mma_tf32<<<gog, 256, SMEM_GEMM>>>(gc, wo, bo, out, MM, EE, EE);
    }
}